// round 16
// baseline (speedup 1.0000x reference)
#include <cuda_runtime.h>
#include <cuda_fp16.h>
#include <cstdint>

// Shapes (fixed): B=2, S=2048, D=1024, H=16, d=64
// head h of batch b = contiguous block (b*2048 + h*128)*1024 viewed as [2048,64] row-major
// d_out = [ proj : 4194304 f32 ][ attn : 134217728 f32 ]

#define PROJ_ELEMS 4194304LL
#define HEAD_STRIDE 131072LL
#define ATTN_STRIDE 4194304LL

// ---------------- persistent device-global scratch ----------------
__device__ __half g_pre16[12582912];   // pre_q|pre_k|pre_v
__device__ __half g_W16[3145728];      // Wq|Wk|Wv
__device__ __half g_Wo16[1048576];
__device__ float  g_bias3[3072];       // bq|bk|bv
__device__ __half g_QKV16[12582912];   // Q|K|V
__device__ __half g_Vt16[4194304];     // V transposed [head][64][2048]
__device__ __half g_O16[4194304];
__device__ __half g_E16[134217728];    // e = exp(s - tileMax), fp16
__device__ float  g_sm[1048576];       // per (head,row,colTile) tile row-max
__device__ float  g_ss[1048576];       // per (head,row,colTile) tile expsum

// ---------------- helpers ----------------
__device__ __forceinline__ uint32_t smem_u32(const void* p) {
    return (uint32_t)__cvta_generic_to_shared(p);
}
__device__ __forceinline__ void cpa16(void* s, const void* g) {
    asm volatile("cp.async.cg.shared.global [%0], [%1], 16;"
                 :: "r"(smem_u32(s)), "l"(__cvta_generic_to_global(g)));
}
__device__ __forceinline__ void cp_commit() { asm volatile("cp.async.commit_group;"); }
template<int NW> __device__ __forceinline__ void cp_wait() {
    asm volatile("cp.async.wait_group %0;" :: "n"(NW));
}
__device__ __forceinline__ void ldmx4(uint32_t& r0, uint32_t& r1, uint32_t& r2, uint32_t& r3,
                                      uint32_t addr) {
    asm volatile("ldmatrix.sync.aligned.m8n8.x4.shared.b16 {%0,%1,%2,%3}, [%4];"
                 : "=r"(r0), "=r"(r1), "=r"(r2), "=r"(r3) : "r"(addr));
}
__device__ __forceinline__ void mma16h(float* c, const uint32_t* a, const uint32_t* b) {
    asm volatile(
        "mma.sync.aligned.m16n8k16.row.col.f32.f16.f16.f32 "
        "{%0,%1,%2,%3},{%4,%5,%6,%7},{%8,%9},{%0,%1,%2,%3};"
        : "+f"(c[0]), "+f"(c[1]), "+f"(c[2]), "+f"(c[3])
        : "r"(a[0]), "r"(a[1]), "r"(a[2]), "r"(a[3]), "r"(b[0]), "r"(b[1]));
}

// ---------------------------------------------------------------------------
// prep: all 7 fp32->fp16 conversions in ONE launch
// ---------------------------------------------------------------------------
struct CJob { const float4* s; __half* h; int n4; };
struct CJobs { CJob j[7]; };

__global__ void cvt_all(CJobs js)
{
    CJob jb = js.j[blockIdx.y];
    int i = blockIdx.x * blockDim.x + threadIdx.x;
    if (i >= jb.n4) return;
    float4 v = jb.s[i];
    __half2 a = __floats2half2_rn(v.x, v.y);
    __half2 b = __floats2half2_rn(v.z, v.w);
    *(__half2*)(jb.h + 4 * i)     = a;
    *(__half2*)(jb.h + 4 * i + 2) = b;
}

__global__ void biascopy(const float* __restrict__ bq, const float* __restrict__ bk,
                         const float* __restrict__ bv, float* __restrict__ dst)
{
    int i = blockIdx.x * blockDim.x + threadIdx.x;
    if (i < 1024) { dst[i] = bq[i]; dst[1024 + i] = bk[i]; dst[2048 + i] = bv[i]; }
}

// Transpose V per head: [2048,64] -> [64,2048].
__global__ __launch_bounds__(256) void transposeV(
    const __half* __restrict__ V, __half* __restrict__ Vt)
{
    __shared__ __half th[64][72];
    const long head = blockIdx.y;
    const int  k0   = blockIdx.x * 64;
    const __half* in = V + head * HEAD_STRIDE + (long)k0 * 64;
    __half* out = Vt + head * HEAD_STRIDE + k0;

    const int tid = threadIdx.x;
    const int lr = tid >> 2, seg = tid & 3;
    #pragma unroll
    for (int i = 0; i < 2; i++) {
        int col = seg * 16 + i * 8;
        *(uint4*)&th[lr][col] = *(const uint4*)(in + (long)lr * 64 + col);
    }
    __syncthreads();
    #pragma unroll
    for (int i = 0; i < 2; i++) {
        int kk = seg * 16 + i * 8;
        __half e[8];
        #pragma unroll
        for (int j = 0; j < 8; j++) e[j] = th[kk + j][lr];
        *(uint4*)(out + (long)lr * 2048 + kk) = *(uint4*)e;
    }
}

// ---------------------------------------------------------------------------
// gemm1: 1-pass fp16 NT GEMM (fp32 accumulate), cp.async 2-stage, BK=64.
//   EPI=0: fp32 C (+bias).  EPI=1: fp16 Cf (+bias).
//   EPI=2: scores mode — NO C write; e=exp(alpha*s - tileMax) fp16 -> Cf,
//          per-tile row stats (max, expsum) -> smOut/ssOut.
// Block 128x128, 256 threads (8 warps 2x4), warp tile 64x32.
// Row pad 72 halves (64 data + 8) -> conflict-free ldmatrix.
// dyn smem: 2 stages * 2 * 128*72*2 = 73728 B (scores K=64: 1 stage, 36864 B).
// ---------------------------------------------------------------------------
#define PADR 72

template<int EPI>
__global__ __launch_bounds__(256) void gemm1(
    const __half* __restrict__ A, const __half* __restrict__ B,
    const float* __restrict__ bias, float* __restrict__ C, __half* __restrict__ Cf,
    int M, int N, int K, float alpha,
    long zsA, long zsB, long zsC, int zsBias,
    float* __restrict__ smOut, float* __restrict__ ssOut)
{
    extern __shared__ __align__(16) __half sm[];
    const long z = blockIdx.z;
    A += z * zsA; B += z * zsB;
    const float* bz = bias ? bias + (long)z * zsBias : nullptr;

    const int tid = threadIdx.x, warp = tid >> 5, lane = tid & 31;
    const int g = lane >> 2, t = lane & 3, wm = warp >> 2, wn = warp & 3;
    const int lrow = lane & 15, lkof = (lane & 16) >> 1;
    const int rowC = blockIdx.y * 128, colC = blockIdx.x * 128;

    const __half* Ap = A + (long)rowC * K;
    const __half* Bp = B + (long)colC * K;

    float acc[4][4][4];
    #pragma unroll
    for (int mi = 0; mi < 4; mi++)
        #pragma unroll
        for (int ni = 0; ni < 4; ni++)
            #pragma unroll
            for (int r = 0; r < 4; r++) acc[mi][ni][r] = 0.f;

    const int fr = tid >> 3, fs = tid & 7;   // fill: row base, 16B seg (8 segs/row)

    auto load_stage = [&](int stg, int k0) {
        __half* dA = sm + stg * 2 * (128 * PADR);
        __half* dB = dA + 128 * PADR;
        #pragma unroll
        for (int j = 0; j < 4; j++) {
            int row = fr + j * 32;
            cpa16(dA + row * PADR + fs * 8, Ap + (long)row * K + k0 + fs * 8);
            cpa16(dB + row * PADR + fs * 8, Bp + (long)row * K + k0 + fs * 8);
        }
    };

    auto compute = [&](int stg) {
        const __half* bA = sm + stg * 2 * (128 * PADR);
        const __half* bB = bA + 128 * PADR;
        #pragma unroll
        for (int ks = 0; ks < 4; ks++) {
            const int kb = ks * 16 + lkof;
            uint32_t bf[4][2];
            #pragma unroll
            for (int p = 0; p < 2; p++) {
                int n = wn * 32 + p * 16 + lrow;
                uint32_t r0, r1, r2, r3;
                ldmx4(r0, r1, r2, r3, smem_u32(bB + n * PADR + kb));
                bf[2*p][0] = r0; bf[2*p+1][0] = r1; bf[2*p][1] = r2; bf[2*p+1][1] = r3;
            }
            #pragma unroll
            for (int mi = 0; mi < 4; mi++) {
                int mrow = wm * 64 + mi * 16 + lrow;
                uint32_t a[4];
                ldmx4(a[0], a[1], a[2], a[3], smem_u32(bA + mrow * PADR + kb));
                #pragma unroll
                for (int ni = 0; ni < 4; ni++)
                    mma16h(acc[mi][ni], a, bf[ni]);
            }
        }
    };

    const int KT = K >> 6;
    load_stage(0, 0); cp_commit();
    for (int kt = 0; kt < KT; kt++) {
        if (kt + 1 < KT) { load_stage((kt + 1) & 1, (kt + 1) * 64); cp_commit(); cp_wait<1>(); }
        else             { cp_wait<0>(); }
        __syncthreads();
        compute(kt & 1);
        __syncthreads();
    }

    if constexpr (EPI == 0 || EPI == 1) {
        float*  Cz  = (EPI == 0) ? C  + z * zsC : nullptr;
        __half* Cfz = (EPI == 1) ? Cf + z * zsC : nullptr;
        #pragma unroll
        for (int mi = 0; mi < 4; mi++) {
            #pragma unroll
            for (int ni = 0; ni < 4; ni++) {
                int r0 = rowC + wm * 64 + mi * 16 + g;
                int cc = colC + wn * 32 + ni * 8 + 2 * t;
                float b0 = bz ? bz[cc] : 0.f, b1 = bz ? bz[cc + 1] : 0.f;
                float c00 = fmaf(acc[mi][ni][0], alpha, b0);
                float c01 = fmaf(acc[mi][ni][1], alpha, b1);
                float c10 = fmaf(acc[mi][ni][2], alpha, b0);
                float c11 = fmaf(acc[mi][ni][3], alpha, b1);
                if (EPI == 0) {
                    float2 o0 = {c00, c01}, o1 = {c10, c11};
                    *(float2*)(Cz + (long)r0 * N + cc)       = o0;
                    *(float2*)(Cz + (long)(r0 + 8) * N + cc) = o1;
                } else {
                    *(__half2*)(Cfz + (long)r0 * N + cc)       = __floats2half2_rn(c00, c01);
                    *(__half2*)(Cfz + (long)(r0 + 8) * N + cc) = __floats2half2_rn(c10, c11);
                }
            }
        }
    }

    if constexpr (EPI == 2) {
        __shared__ float redm[4][128];
        __shared__ float reds[4][128];
        __shared__ float fM[128];
        // ---- pass A: tile row max ----
        #pragma unroll
        for (int mi = 0; mi < 4; mi++) {
            #pragma unroll
            for (int h = 0; h < 2; h++) {
                float tm = -1e30f;
                #pragma unroll
                for (int ni = 0; ni < 4; ni++) {
                    tm = fmaxf(tm, acc[mi][ni][2*h]);
                    tm = fmaxf(tm, acc[mi][ni][2*h+1]);
                }
                tm *= alpha;
                #pragma unroll
                for (int off = 1; off <= 2; off <<= 1)
                    tm = fmaxf(tm, __shfl_xor_sync(0xffffffffu, tm, off));
                if (t == 0) redm[wn][wm * 64 + mi * 16 + g + h * 8] = tm;
            }
        }
        __syncthreads();
        if (tid < 128)
            fM[tid] = fmaxf(fmaxf(redm[0][tid], redm[1][tid]),
                            fmaxf(redm[2][tid], redm[3][tid]));
        __syncthreads();
        // ---- pass B: e = exp(s - M), store fp16, expsum ----
        __half* Ez = Cf + z * zsC;
        #pragma unroll
        for (int mi = 0; mi < 4; mi++) {
            #pragma unroll
            for (int h = 0; h < 2; h++) {
                int row = wm * 64 + mi * 16 + g + h * 8;
                float Mv = fM[row];
                float ts = 0.f;
                #pragma unroll
                for (int ni = 0; ni < 4; ni++) {
                    float e0 = __expf(fmaf(acc[mi][ni][2*h],   alpha, -Mv));
                    float e1 = __expf(fmaf(acc[mi][ni][2*h+1], alpha, -Mv));
                    ts += e0 + e1;
                    int cc = colC + wn * 32 + ni * 8 + 2 * t;
                    *(__half2*)(Ez + (long)(rowC + row) * N + cc) = __floats2half2_rn(e0, e1);
                }
                #pragma unroll
                for (int off = 1; off <= 2; off <<= 1)
                    ts += __shfl_xor_sync(0xffffffffu, ts, off);
                if (t == 0) reds[wn][row] = ts;
            }
        }
        __syncthreads();
        if (tid < 128) {
            float S = reds[0][tid] + reds[1][tid] + reds[2][tid] + reds[3][tid];
            long idx = (((long)z * 2048) + (rowC + tid)) * 16 + blockIdx.x;
            smOut[idx] = fM[tid];
            ssOut[idx] = S;
        }
    }
}

// ---------------------------------------------------------------------------
// gemm_pv: exp-free fused normalize + (P @ V) per (b,h). BK=64.
//   Reads e (fp16), prologue builds per-(row,tile) factor f = exp(m_t - M)/S;
//   fill path: p = e*f, fp32 p -> attn (output), fp16 p -> smem,
//   1-pass fp16 MMA vs pre-transposed V^T. Emits fp16 O.
// Block 128x64, 256 thr. dyn smem = (2*128 + 2*64)*PADR halves = 55296 B.
// ---------------------------------------------------------------------------
__global__ __launch_bounds__(256) void gemm_pv(
    const __half* __restrict__ E, float* __restrict__ attn,
    const __half* __restrict__ Vt, __half* __restrict__ O,
    const float* __restrict__ gsm, const float* __restrict__ gss)
{
    extern __shared__ __align__(16) __half smb[];
    __half* sP = smb;                       // [2][128*PADR]
    __half* sV = smb + 2 * 128 * PADR;      // [2][64*PADR]
    __shared__ float sfac[128][17];

    const long z = blockIdx.z;
    const int  rb = blockIdx.y;
    const __half* Ep = E + z * ATTN_STRIDE + (long)rb * 128 * 2048;
    float* Pp = attn + z * ATTN_STRIDE + (long)rb * 128 * 2048;
    const __half* Vp = Vt + z * HEAD_STRIDE;
    __half* Oz = O + z * HEAD_STRIDE + (long)rb * 128 * 64;

    const int tid = threadIdx.x, warp = tid >> 5, lane = tid & 31;
    const int g = lane >> 2, t = lane & 3, wm = warp >> 2, wn = warp & 3;
    const int lrow = lane & 15, lkof = (lane & 16) >> 1;

    if (tid < 128) {
        int rowg = rb * 128 + tid;
        const float* pm = gsm + ((((long)z * 2048) + rowg) << 4);
        const float* ps = gss + ((((long)z * 2048) + rowg) << 4);
        float M = pm[0];
        #pragma unroll
        for (int ct = 1; ct < 16; ct++) M = fmaxf(M, pm[ct]);
        float w[16];
        float S = 0.f;
        #pragma unroll
        for (int ct = 0; ct < 16; ct++) {
            w[ct] = __expf(pm[ct] - M);
            S += ps[ct] * w[ct];
        }
        float inv = 1.f / S;
        #pragma unroll
        for (int ct = 0; ct < 16; ct++) sfac[tid][ct] = w[ct] * inv;
    }
    __syncthreads();

    float acc[4][2][4];
    #pragma unroll
    for (int mi = 0; mi < 4; mi++)
        #pragma unroll
        for (int ni = 0; ni < 2; ni++)
            #pragma unroll
            for (int r = 0; r < 4; r++) acc[mi][ni][r] = 0.f;

    const int er = tid >> 3, es = tid & 7;   // E fill: row base, 8-half seg (8/row)
    const int nr = tid >> 3, ns = tid & 7;   // V fill: 64 rows x 8 segs = 512 / 256 = 2ea

    uint4 eregs[4];
    auto ldE = [&](int k0) {
        #pragma unroll
        for (int i = 0; i < 4; i++) {
            int row = er + i * 32;
            eregs[i] = *(const uint4*)(Ep + (long)row * 2048 + k0 + es * 8);
        }
    };
    auto stsP = [&](int stg, int k0) {
        __half* d = sP + stg * 128 * PADR;
        const int tile = k0 >> 7;
        #pragma unroll
        for (int i = 0; i < 4; i++) {
            int row = er + i * 32;
            float f = sfac[row][tile];
            __half eh[8];
            *(uint4*)eh = eregs[i];
            float p[8];
            #pragma unroll
            for (int c = 0; c < 8; c++) p[c] = __half2float(eh[c]) * f;
            float4 o0 = {p[0], p[1], p[2], p[3]};
            float4 o1 = {p[4], p[5], p[6], p[7]};
            *(float4*)(Pp + (long)row * 2048 + k0 + es * 8)     = o0;
            *(float4*)(Pp + (long)row * 2048 + k0 + es * 8 + 4) = o1;
            __half2* ds = (__half2*)(d + row * PADR + es * 8);
            ds[0] = __floats2half2_rn(p[0], p[1]);
            ds[1] = __floats2half2_rn(p[2], p[3]);
            ds[2] = __floats2half2_rn(p[4], p[5]);
            ds[3] = __floats2half2_rn(p[6], p[7]);
        }
    };
    auto loadV = [&](int stg, int k0) {
        __half* d = sV + stg * 64 * PADR;
        #pragma unroll
        for (int i = 0; i < 2; i++) {
            int row = nr + i * 32;
            cpa16(d + row * PADR + ns * 8, Vp + (long)row * 2048 + k0 + ns * 8);
        }
    };

    auto compute = [&](int stg) {
        const __half* bP = sP + stg * 128 * PADR;
        const __half* bV = sV + stg * 64 * PADR;
        #pragma unroll
        for (int ks = 0; ks < 4; ks++) {
            const int kb = ks * 16 + lkof;
            uint32_t bv[2][2];
            {
                int n = wn * 16 + lrow;
                uint32_t r0, r1, r2, r3;
                ldmx4(r0, r1, r2, r3, smem_u32(bV + n * PADR + kb));
                bv[0][0] = r0; bv[1][0] = r1; bv[0][1] = r2; bv[1][1] = r3;
            }
            #pragma unroll
            for (int mi = 0; mi < 4; mi++) {
                int m = wm * 64 + mi * 16 + lrow;
                uint32_t p[4];
                ldmx4(p[0], p[1], p[2], p[3], smem_u32(bP + m * PADR + kb));
                mma16h(acc[mi][0], p, bv[0]);
                mma16h(acc[mi][1], p, bv[1]);
            }
        }
    };

    ldE(0);
    loadV(0, 0); cp_commit();
    for (int kt = 0; kt < 32; kt++) {
        stsP(kt & 1, kt * 64);
        cp_wait<0>();
        __syncthreads();
        if (kt + 1 < 32) {
            ldE((kt + 1) * 64);
            loadV((kt + 1) & 1, (kt + 1) * 64); cp_commit();
        }
        compute(kt & 1);
        __syncthreads();
    }

    #pragma unroll
    for (int mi = 0; mi < 4; mi++) {
        #pragma unroll
        for (int ni = 0; ni < 2; ni++) {
            int r0 = wm * 64 + mi * 16 + g;
            int cc = wn * 16 + ni * 8 + 2 * t;
            *(__half2*)(Oz + (long)r0 * 64 + cc)       = __floats2half2_rn(acc[mi][ni][0], acc[mi][ni][1]);
            *(__half2*)(Oz + (long)(r0 + 8) * 64 + cc) = __floats2half2_rn(acc[mi][ni][2], acc[mi][ni][3]);
        }
    }
}

// ---------------------------------------------------------------------------
extern "C" void kernel_launch(void* const* d_in, const int* in_sizes, int n_in,
                              void* d_out, int out_size)
{
    const float* pre_q = (const float*)d_in[0];
    const float* pre_k = (const float*)d_in[1];
    const float* pre_v = (const float*)d_in[2];
    const float* Wq = (const float*)d_in[3];
    const float* bq = (const float*)d_in[4];
    const float* Wk = (const float*)d_in[5];
    const float* bk = (const float*)d_in[6];
    const float* Wv = (const float*)d_in[7];
    const float* bv = (const float*)d_in[8];
    const float* Wo = (const float*)d_in[9];
    const float* bo = (const float*)d_in[10];

    float* proj = (float*)d_out;
    float* attn = proj + PROJ_ELEMS;

    __half *pre16, *W16, *Wo16, *QKV16, *Vt16, *O16, *E16;
    float *bias3, *smp, *ssp;
    cudaGetSymbolAddress((void**)&pre16, g_pre16);
    cudaGetSymbolAddress((void**)&W16, g_W16);
    cudaGetSymbolAddress((void**)&Wo16, g_Wo16);
    cudaGetSymbolAddress((void**)&bias3, g_bias3);
    cudaGetSymbolAddress((void**)&QKV16, g_QKV16);
    cudaGetSymbolAddress((void**)&Vt16, g_Vt16);
    cudaGetSymbolAddress((void**)&O16, g_O16);
    cudaGetSymbolAddress((void**)&E16, g_E16);
    cudaGetSymbolAddress((void**)&smp, g_sm);
    cudaGetSymbolAddress((void**)&ssp, g_ss);

    static bool attr_done = false;
    if (!attr_done) {
        cudaFuncSetAttribute(gemm1<0>, cudaFuncAttributeMaxDynamicSharedMemorySize, 73728);
        cudaFuncSetAttribute(gemm1<1>, cudaFuncAttributeMaxDynamicSharedMemorySize, 73728);
        cudaFuncSetAttribute(gemm1<2>, cudaFuncAttributeMaxDynamicSharedMemorySize, 36864);
        cudaFuncSetAttribute(gemm_pv,  cudaFuncAttributeMaxDynamicSharedMemorySize, 55296);
        attr_done = true;
    }

    // launch 0: biases
    biascopy<<<4, 256>>>(bq, bk, bv, bias3);

    // launch 1: all 7 fp32->fp16 conversions
    CJobs js;
    js.j[0] = { (const float4*)pre_q, pre16,           1048576 };
    js.j[1] = { (const float4*)pre_k, pre16 + 4194304, 1048576 };
    js.j[2] = { (const float4*)pre_v, pre16 + 8388608, 1048576 };
    js.j[3] = { (const float4*)Wq,    W16,             262144 };
    js.j[4] = { (const float4*)Wk,    W16 + 1048576,   262144 };
    js.j[5] = { (const float4*)Wv,    W16 + 2097152,   262144 };
    js.j[6] = { (const float4*)Wo,    Wo16,            262144 };
    cvt_all<<<dim3(4096, 7), 256>>>(js);

    // launch 2: QKV projections (merged z=3), fp16 outputs
    gemm1<1><<<dim3(8, 32, 3), 256, 73728>>>(
        pre16, W16, bias3, nullptr, QKV16,
        4096, 1024, 1024, 1.f, 4194304, 1048576, 4194304, 1024, nullptr, nullptr);

    // launch 3: transpose V per head
    transposeV<<<dim3(32, 32), 256>>>(QKV16 + 8388608, Vt16);

    // launch 4: scores -> e (fp16) + per-tile stats (single K=64 slab)
    gemm1<2><<<dim3(16, 16, 32), 256, 36864>>>(
        QKV16, QKV16 + 4194304, nullptr, nullptr, E16,
        2048, 2048, 64, 0.125f, HEAD_STRIDE, HEAD_STRIDE, ATTN_STRIDE, 0, smp, ssp);

    // launch 5: exp-free normalize + P@V (writes normalized attn, fp16 O)
    gemm_pv<<<dim3(1, 16, 32), 256, 55296>>>(E16, attn, Vt16, O16, smp, ssp);

    // launch 6: output projection
    gemm1<0><<<dim3(8, 32, 1), 256, 73728>>>(
        O16, Wo16, bo, proj, nullptr,
        4096, 1024, 1024, 1.f, 0, 0, 0, 0, nullptr, nullptr);
}

// round 17
// speedup vs baseline: 1.3290x; 1.3290x over previous
#include <cuda_runtime.h>
#include <cuda_fp16.h>
#include <cstdint>

// Shapes (fixed): B=2, S=2048, D=1024, H=16, d=64
// head h of batch b = contiguous block (b*2048 + h*128)*1024 viewed as [2048,64] row-major
// d_out = [ proj : 4194304 f32 ][ attn : 134217728 f32 ]

#define PROJ_ELEMS 4194304LL
#define HEAD_STRIDE 131072LL
#define ATTN_STRIDE 4194304LL

// ---------------- persistent device-global scratch ----------------
__device__ __half g_pre16[12582912];   // pre_q|pre_k|pre_v
__device__ __half g_W16[3145728];      // Wq|Wk|Wv
__device__ __half g_Wo16[1048576];
__device__ float  g_bias3[3072];       // bq|bk|bv
__device__ __half g_QKV16[12582912];   // Q|K|V
__device__ __half g_Vt16[4194304];     // V transposed [head][64][2048]
__device__ __half g_O16[4194304];
__device__ __half g_E16[134217728];    // e = exp(s - tileMax), fp16
__device__ float  g_sm[1048576];       // per (head,row,colTile) tile row-max
__device__ float  g_ss[1048576];       // per (head,row,colTile) tile expsum

// ---------------- helpers ----------------
__device__ __forceinline__ uint32_t smem_u32(const void* p) {
    return (uint32_t)__cvta_generic_to_shared(p);
}
__device__ __forceinline__ void cpa16(void* s, const void* g) {
    asm volatile("cp.async.cg.shared.global [%0], [%1], 16;"
                 :: "r"(smem_u32(s)), "l"(__cvta_generic_to_global(g)));
}
__device__ __forceinline__ void cp_commit() { asm volatile("cp.async.commit_group;"); }
template<int NW> __device__ __forceinline__ void cp_wait() {
    asm volatile("cp.async.wait_group %0;" :: "n"(NW));
}
__device__ __forceinline__ void ldmx4(uint32_t& r0, uint32_t& r1, uint32_t& r2, uint32_t& r3,
                                      uint32_t addr) {
    asm volatile("ldmatrix.sync.aligned.m8n8.x4.shared.b16 {%0,%1,%2,%3}, [%4];"
                 : "=r"(r0), "=r"(r1), "=r"(r2), "=r"(r3) : "r"(addr));
}
__device__ __forceinline__ void mma16h(float* c, const uint32_t* a, const uint32_t* b) {
    asm volatile(
        "mma.sync.aligned.m16n8k16.row.col.f32.f16.f16.f32 "
        "{%0,%1,%2,%3},{%4,%5,%6,%7},{%8,%9},{%0,%1,%2,%3};"
        : "+f"(c[0]), "+f"(c[1]), "+f"(c[2]), "+f"(c[3])
        : "r"(a[0]), "r"(a[1]), "r"(a[2]), "r"(a[3]), "r"(b[0]), "r"(b[1]));
}
// streaming (evict-first) 16B store / load
__device__ __forceinline__ void stcs16(void* p, uint4 v) {
    asm volatile("st.global.cs.v4.u32 [%0], {%1,%2,%3,%4};"
                 :: "l"(__cvta_generic_to_global(p)), "r"(v.x), "r"(v.y), "r"(v.z), "r"(v.w)
                 : "memory");
}
__device__ __forceinline__ uint4 ldcs16(const void* p) {
    uint4 v;
    asm volatile("ld.global.cs.v4.u32 {%0,%1,%2,%3}, [%4];"
                 : "=r"(v.x), "=r"(v.y), "=r"(v.z), "=r"(v.w)
                 : "l"(__cvta_generic_to_global(p)));
    return v;
}
__device__ __forceinline__ void stcs8(void* p, uint2 v) {
    asm volatile("st.global.cs.v2.u32 [%0], {%1,%2};"
                 :: "l"(__cvta_generic_to_global(p)), "r"(v.x), "r"(v.y) : "memory");
}

#define SPAD 40   // smem row stride (halves): 32 data + 8 pad -> conflict-free ldmatrix

// ---------------------------------------------------------------------------
// prep: all 7 fp32->fp16 conversions in ONE launch
// ---------------------------------------------------------------------------
struct CJob { const float4* s; __half* h; int n4; };
struct CJobs { CJob j[7]; };

__global__ void cvt_all(CJobs js)
{
    CJob jb = js.j[blockIdx.y];
    int i = blockIdx.x * blockDim.x + threadIdx.x;
    if (i >= jb.n4) return;
    float4 v = jb.s[i];
    __half2 a = __floats2half2_rn(v.x, v.y);
    __half2 b = __floats2half2_rn(v.z, v.w);
    *(__half2*)(jb.h + 4 * i)     = a;
    *(__half2*)(jb.h + 4 * i + 2) = b;
}

__global__ void biascopy(const float* __restrict__ bq, const float* __restrict__ bk,
                         const float* __restrict__ bv, float* __restrict__ dst)
{
    int i = blockIdx.x * blockDim.x + threadIdx.x;
    if (i < 1024) { dst[i] = bq[i]; dst[1024 + i] = bk[i]; dst[2048 + i] = bv[i]; }
}

// Transpose V per head: [2048,64] -> [64,2048].
__global__ __launch_bounds__(256) void transposeV(
    const __half* __restrict__ V, __half* __restrict__ Vt)
{
    __shared__ __half th[64][72];
    const long head = blockIdx.y;
    const int  k0   = blockIdx.x * 64;
    const __half* in = V + head * HEAD_STRIDE + (long)k0 * 64;
    __half* out = Vt + head * HEAD_STRIDE + k0;

    const int tid = threadIdx.x;
    const int lr = tid >> 2, seg = tid & 3;
    #pragma unroll
    for (int i = 0; i < 2; i++) {
        int col = seg * 16 + i * 8;
        *(uint4*)&th[lr][col] = *(const uint4*)(in + (long)lr * 64 + col);
    }
    __syncthreads();
    #pragma unroll
    for (int i = 0; i < 2; i++) {
        int kk = seg * 16 + i * 8;
        __half e[8];
        #pragma unroll
        for (int j = 0; j < 8; j++) e[j] = th[kk + j][lr];
        *(uint4*)(out + (long)lr * 2048 + kk) = *(uint4*)e;
    }
}

// ---------------------------------------------------------------------------
// gemm1: 1-pass fp16 NT GEMM (fp32 accumulate), cp.async 2-stage, BK=32.
//   EPI=0: fp32 C (+bias).  EPI=1: fp16 Cf (+bias).
//   EPI=2: scores mode — NO C write; e=exp(alpha*s - tileMax) fp16 -> Cf (.cs),
//          per-tile row stats (max, expsum) -> smOut/ssOut.
// Block 128x128, 256 threads (8 warps 2x4), warp tile 64x32. dyn smem 40960 B.
// ---------------------------------------------------------------------------
template<int EPI>
__global__ __launch_bounds__(256) void gemm1(
    const __half* __restrict__ A, const __half* __restrict__ B,
    const float* __restrict__ bias, float* __restrict__ C, __half* __restrict__ Cf,
    int M, int N, int K, float alpha,
    long zsA, long zsB, long zsC, int zsBias,
    float* __restrict__ smOut, float* __restrict__ ssOut)
{
    extern __shared__ __align__(16) __half sm[];
    const long z = blockIdx.z;
    A += z * zsA; B += z * zsB;
    const float* bz = bias ? bias + (long)z * zsBias : nullptr;

    const int tid = threadIdx.x, warp = tid >> 5, lane = tid & 31;
    const int g = lane >> 2, t = lane & 3, wm = warp >> 2, wn = warp & 3;
    const int lrow = lane & 15, lkof = (lane & 16) >> 1;
    const int rowC = blockIdx.y * 128, colC = blockIdx.x * 128;

    const __half* Ap = A + (long)rowC * K;
    const __half* Bp = B + (long)colC * K;

    float acc[4][4][4];
    #pragma unroll
    for (int mi = 0; mi < 4; mi++)
        #pragma unroll
        for (int ni = 0; ni < 4; ni++)
            #pragma unroll
            for (int r = 0; r < 4; r++) acc[mi][ni][r] = 0.f;

    const int rr = tid >> 2, ss = tid & 3;

    auto load_stage = [&](int stg, int k0) {
        __half* dA = sm + stg * 2 * (128 * SPAD);
        __half* dB = dA + 128 * SPAD;
        cpa16(dA + rr * SPAD + ss * 8,          Ap + (long)rr * K + k0 + ss * 8);
        cpa16(dA + (rr + 64) * SPAD + ss * 8,   Ap + (long)(rr + 64) * K + k0 + ss * 8);
        cpa16(dB + rr * SPAD + ss * 8,          Bp + (long)rr * K + k0 + ss * 8);
        cpa16(dB + (rr + 64) * SPAD + ss * 8,   Bp + (long)(rr + 64) * K + k0 + ss * 8);
    };

    auto compute = [&](int stg) {
        const __half* bA = sm + stg * 2 * (128 * SPAD);
        const __half* bB = bA + 128 * SPAD;
        #pragma unroll
        for (int ks = 0; ks < 2; ks++) {
            const int kb = ks * 16 + lkof;
            uint32_t bf[4][2];
            #pragma unroll
            for (int p = 0; p < 2; p++) {
                int n = wn * 32 + p * 16 + lrow;
                uint32_t r0, r1, r2, r3;
                ldmx4(r0, r1, r2, r3, smem_u32(bB + n * SPAD + kb));
                bf[2*p][0] = r0; bf[2*p+1][0] = r1; bf[2*p][1] = r2; bf[2*p+1][1] = r3;
            }
            #pragma unroll
            for (int mi = 0; mi < 4; mi++) {
                int mrow = wm * 64 + mi * 16 + lrow;
                uint32_t a[4];
                ldmx4(a[0], a[1], a[2], a[3], smem_u32(bA + mrow * SPAD + kb));
                #pragma unroll
                for (int ni = 0; ni < 4; ni++)
                    mma16h(acc[mi][ni], a, bf[ni]);
            }
        }
    };

    const int KT = K >> 5;
    load_stage(0, 0); cp_commit();
    for (int kt = 0; kt < KT; kt++) {
        if (kt + 1 < KT) { load_stage((kt + 1) & 1, (kt + 1) * 32); cp_commit(); cp_wait<1>(); }
        else             { cp_wait<0>(); }
        __syncthreads();
        compute(kt & 1);
        __syncthreads();
    }

    if constexpr (EPI == 0 || EPI == 1) {
        float*  Cz  = (EPI == 0) ? C  + z * zsC : nullptr;
        __half* Cfz = (EPI == 1) ? Cf + z * zsC : nullptr;
        #pragma unroll
        for (int mi = 0; mi < 4; mi++) {
            #pragma unroll
            for (int ni = 0; ni < 4; ni++) {
                int r0 = rowC + wm * 64 + mi * 16 + g;
                int cc = colC + wn * 32 + ni * 8 + 2 * t;
                float b0 = bz ? bz[cc] : 0.f, b1 = bz ? bz[cc + 1] : 0.f;
                float c00 = fmaf(acc[mi][ni][0], alpha, b0);
                float c01 = fmaf(acc[mi][ni][1], alpha, b1);
                float c10 = fmaf(acc[mi][ni][2], alpha, b0);
                float c11 = fmaf(acc[mi][ni][3], alpha, b1);
                if (EPI == 0) {
                    float2 o0 = {c00, c01}, o1 = {c10, c11};
                    *(float2*)(Cz + (long)r0 * N + cc)       = o0;
                    *(float2*)(Cz + (long)(r0 + 8) * N + cc) = o1;
                } else {
                    *(__half2*)(Cfz + (long)r0 * N + cc)       = __floats2half2_rn(c00, c01);
                    *(__half2*)(Cfz + (long)(r0 + 8) * N + cc) = __floats2half2_rn(c10, c11);
                }
            }
        }
    }

    if constexpr (EPI == 2) {
        __shared__ float redm[4][128];
        __shared__ float reds[4][128];
        __shared__ float fM[128];
        // ---- pass A: tile row max ----
        #pragma unroll
        for (int mi = 0; mi < 4; mi++) {
            #pragma unroll
            for (int h = 0; h < 2; h++) {
                float tm = -1e30f;
                #pragma unroll
                for (int ni = 0; ni < 4; ni++) {
                    tm = fmaxf(tm, acc[mi][ni][2*h]);
                    tm = fmaxf(tm, acc[mi][ni][2*h+1]);
                }
                tm *= alpha;
                #pragma unroll
                for (int off = 1; off <= 2; off <<= 1)
                    tm = fmaxf(tm, __shfl_xor_sync(0xffffffffu, tm, off));
                if (t == 0) redm[wn][wm * 64 + mi * 16 + g + h * 8] = tm;
            }
        }
        __syncthreads();
        if (tid < 128)
            fM[tid] = fmaxf(fmaxf(redm[0][tid], redm[1][tid]),
                            fmaxf(redm[2][tid], redm[3][tid]));
        __syncthreads();
        // ---- pass B: e = exp(s - M), store fp16 (.cs), expsum ----
        __half* Ez = Cf + z * zsC;
        #pragma unroll
        for (int mi = 0; mi < 4; mi++) {
            #pragma unroll
            for (int h = 0; h < 2; h++) {
                int row = wm * 64 + mi * 16 + g + h * 8;
                float Mv = fM[row];
                float ts = 0.f;
                #pragma unroll
                for (int ni = 0; ni < 4; ni++) {
                    float e0 = __expf(fmaf(acc[mi][ni][2*h],   alpha, -Mv));
                    float e1 = __expf(fmaf(acc[mi][ni][2*h+1], alpha, -Mv));
                    ts += e0 + e1;
                    int cc = colC + wn * 32 + ni * 8 + 2 * t;
                    __half2 hv = __floats2half2_rn(e0, e1);
                    uint32_t hb = *(uint32_t*)&hv;
                    asm volatile("st.global.cs.u32 [%0], %1;"
                                 :: "l"(__cvta_generic_to_global(Ez + (long)(rowC + row) * N + cc)),
                                    "r"(hb) : "memory");
                }
                #pragma unroll
                for (int off = 1; off <= 2; off <<= 1)
                    ts += __shfl_xor_sync(0xffffffffu, ts, off);
                if (t == 0) reds[wn][row] = ts;
            }
        }
        __syncthreads();
        if (tid < 128) {
            float S = reds[0][tid] + reds[1][tid] + reds[2][tid] + reds[3][tid];
            long idx = (((long)z * 2048) + (rowC + tid)) * 16 + blockIdx.x;
            smOut[idx] = fM[tid];
            ssOut[idx] = S;
        }
    }
}

// ---------------------------------------------------------------------------
// gemm_pv: exp-free fused normalize + (P @ V) per (b,h). BK=32.
//   Reads e (fp16, .cs), prologue builds per-(row,tile) factor f = exp(m_t-M)/S;
//   fill path: p = e*f, fp32 p -> attn via .cs (output, never re-read),
//   fp16 p -> smem, 1-pass fp16 MMA vs pre-transposed V^T. Emits fp16 O.
// Block 128x64, 256 thr. dyn smem = (2*128 + 2*64)*SPAD halves = 30720 B.
// ---------------------------------------------------------------------------
__global__ __launch_bounds__(256) void gemm_pv(
    const __half* __restrict__ E, float* __restrict__ attn,
    const __half* __restrict__ Vt, __half* __restrict__ O,
    const float* __restrict__ gsm, const float* __restrict__ gss)
{
    extern __shared__ __align__(16) __half smb[];
    __half* sP = smb;                       // [2][128*SPAD]
    __half* sV = smb + 2 * 128 * SPAD;      // [2][64*SPAD]
    __shared__ float sfac[128][17];

    const long z = blockIdx.z;
    const int  rb = blockIdx.y;
    const __half* Ep = E + z * ATTN_STRIDE + (long)rb * 128 * 2048;
    float* Pp = attn + z * ATTN_STRIDE + (long)rb * 128 * 2048;
    const __half* Vp = Vt + z * HEAD_STRIDE;
    __half* Oz = O + z * HEAD_STRIDE + (long)rb * 128 * 64;

    const int tid = threadIdx.x, warp = tid >> 5, lane = tid & 31;
    const int g = lane >> 2, t = lane & 3, wm = warp >> 2, wn = warp & 3;
    const int lrow = lane & 15, lkof = (lane & 16) >> 1;

    if (tid < 128) {
        int rowg = rb * 128 + tid;
        const float* pm = gsm + ((((long)z * 2048) + rowg) << 4);
        const float* ps = gss + ((((long)z * 2048) + rowg) << 4);
        float M = pm[0];
        #pragma unroll
        for (int ct = 1; ct < 16; ct++) M = fmaxf(M, pm[ct]);
        float w[16];
        float S = 0.f;
        #pragma unroll
        for (int ct = 0; ct < 16; ct++) {
            w[ct] = __expf(pm[ct] - M);
            S += ps[ct] * w[ct];
        }
        float inv = 1.f / S;
        #pragma unroll
        for (int ct = 0; ct < 16; ct++) sfac[tid][ct] = w[ct] * inv;
    }
    __syncthreads();

    float acc[4][2][4];
    #pragma unroll
    for (int mi = 0; mi < 4; mi++)
        #pragma unroll
        for (int ni = 0; ni < 2; ni++)
            #pragma unroll
            for (int r = 0; r < 4; r++) acc[mi][ni][r] = 0.f;

    const int nr = tid >> 2, ns = tid & 3;   // V loader

    uint4 eregs[2];
    auto ldE = [&](int k0) {
        #pragma unroll
        for (int i = 0; i < 2; i++) {
            int idx = tid + i * 256, row = idx >> 2, seg = idx & 3;
            eregs[i] = ldcs16(Ep + (long)row * 2048 + k0 + seg * 8);
        }
    };
    auto stsP = [&](int stg, int k0) {
        __half* d = sP + stg * 128 * SPAD;
        const int tile = k0 >> 7;
        #pragma unroll
        for (int i = 0; i < 2; i++) {
            int idx = tid + i * 256, row = idx >> 2, seg = idx & 3;
            float f = sfac[row][tile];
            __half eh[8];
            *(uint4*)eh = eregs[i];
            float p[8];
            #pragma unroll
            for (int c = 0; c < 8; c++) p[c] = __half2float(eh[c]) * f;
            float4 o0 = {p[0], p[1], p[2], p[3]};
            float4 o1 = {p[4], p[5], p[6], p[7]};
            stcs16(Pp + (long)row * 2048 + k0 + seg * 8,     *(uint4*)&o0);
            stcs16(Pp + (long)row * 2048 + k0 + seg * 8 + 4, *(uint4*)&o1);
            __half2* ds = (__half2*)(d + row * SPAD + seg * 8);
            ds[0] = __floats2half2_rn(p[0], p[1]);
            ds[1] = __floats2half2_rn(p[2], p[3]);
            ds[2] = __floats2half2_rn(p[4], p[5]);
            ds[3] = __floats2half2_rn(p[6], p[7]);
        }
    };
    auto loadV = [&](int stg, int k0) {
        cpa16(sV + stg * 64 * SPAD + nr * SPAD + ns * 8, Vp + (long)nr * 2048 + k0 + ns * 8);
    };

    auto compute = [&](int stg) {
        const __half* bP = sP + stg * 128 * SPAD;
        const __half* bV = sV + stg * 64 * SPAD;
        #pragma unroll
        for (int ks = 0; ks < 2; ks++) {
            const int kb = ks * 16 + lkof;
            uint32_t bv[2][2];
            {
                int n = wn * 16 + lrow;
                uint32_t r0, r1, r2, r3;
                ldmx4(r0, r1, r2, r3, smem_u32(bV + n * SPAD + kb));
                bv[0][0] = r0; bv[1][0] = r1; bv[0][1] = r2; bv[1][1] = r3;
            }
            #pragma unroll
            for (int mi = 0; mi < 4; mi++) {
                int m = wm * 64 + mi * 16 + lrow;
                uint32_t p[4];
                ldmx4(p[0], p[1], p[2], p[3], smem_u32(bP + m * SPAD + kb));
                mma16h(acc[mi][0], p, bv[0]);
                mma16h(acc[mi][1], p, bv[1]);
            }
        }
    };

    ldE(0);
    loadV(0, 0); cp_commit();
    for (int kt = 0; kt < 64; kt++) {
        stsP(kt & 1, kt * 32);
        cp_wait<0>();
        __syncthreads();
        if (kt + 1 < 64) {
            ldE((kt + 1) * 32);
            loadV((kt + 1) & 1, (kt + 1) * 32); cp_commit();
        }
        compute(kt & 1);
        __syncthreads();
    }

    #pragma unroll
    for (int mi = 0; mi < 4; mi++) {
        #pragma unroll
        for (int ni = 0; ni < 2; ni++) {
            int r0 = wm * 64 + mi * 16 + g;
            int cc = wn * 16 + ni * 8 + 2 * t;
            *(__half2*)(Oz + (long)r0 * 64 + cc)       = __floats2half2_rn(acc[mi][ni][0], acc[mi][ni][1]);
            *(__half2*)(Oz + (long)(r0 + 8) * 64 + cc) = __floats2half2_rn(acc[mi][ni][2], acc[mi][ni][3]);
        }
    }
}

// ---------------------------------------------------------------------------
extern "C" void kernel_launch(void* const* d_in, const int* in_sizes, int n_in,
                              void* d_out, int out_size)
{
    const float* pre_q = (const float*)d_in[0];
    const float* pre_k = (const float*)d_in[1];
    const float* pre_v = (const float*)d_in[2];
    const float* Wq = (const float*)d_in[3];
    const float* bq = (const float*)d_in[4];
    const float* Wk = (const float*)d_in[5];
    const float* bk = (const float*)d_in[6];
    const float* Wv = (const float*)d_in[7];
    const float* bv = (const float*)d_in[8];
    const float* Wo = (const float*)d_in[9];
    const float* bo = (const float*)d_in[10];

    float* proj = (float*)d_out;
    float* attn = proj + PROJ_ELEMS;

    __half *pre16, *W16, *Wo16, *QKV16, *Vt16, *O16, *E16;
    float *bias3, *smp, *ssp;
    cudaGetSymbolAddress((void**)&pre16, g_pre16);
    cudaGetSymbolAddress((void**)&W16, g_W16);
    cudaGetSymbolAddress((void**)&Wo16, g_Wo16);
    cudaGetSymbolAddress((void**)&bias3, g_bias3);
    cudaGetSymbolAddress((void**)&QKV16, g_QKV16);
    cudaGetSymbolAddress((void**)&Vt16, g_Vt16);
    cudaGetSymbolAddress((void**)&O16, g_O16);
    cudaGetSymbolAddress((void**)&E16, g_E16);
    cudaGetSymbolAddress((void**)&smp, g_sm);
    cudaGetSymbolAddress((void**)&ssp, g_ss);

    static bool attr_done = false;
    if (!attr_done) {
        cudaFuncSetAttribute(gemm1<0>, cudaFuncAttributeMaxDynamicSharedMemorySize, 40960);
        cudaFuncSetAttribute(gemm1<1>, cudaFuncAttributeMaxDynamicSharedMemorySize, 40960);
        cudaFuncSetAttribute(gemm1<2>, cudaFuncAttributeMaxDynamicSharedMemorySize, 40960);
        cudaFuncSetAttribute(gemm_pv,  cudaFuncAttributeMaxDynamicSharedMemorySize, 30720);
        attr_done = true;
    }

    // launch 0: biases
    biascopy<<<4, 256>>>(bq, bk, bv, bias3);

    // launch 1: all 7 fp32->fp16 conversions
    CJobs js;
    js.j[0] = { (const float4*)pre_q, pre16,           1048576 };
    js.j[1] = { (const float4*)pre_k, pre16 + 4194304, 1048576 };
    js.j[2] = { (const float4*)pre_v, pre16 + 8388608, 1048576 };
    js.j[3] = { (const float4*)Wq,    W16,             262144 };
    js.j[4] = { (const float4*)Wk,    W16 + 1048576,   262144 };
    js.j[5] = { (const float4*)Wv,    W16 + 2097152,   262144 };
    js.j[6] = { (const float4*)Wo,    Wo16,            262144 };
    cvt_all<<<dim3(4096, 7), 256>>>(js);

    // launch 2: QKV projections (merged z=3), fp16 outputs
    gemm1<1><<<dim3(8, 32, 3), 256, 40960>>>(
        pre16, W16, bias3, nullptr, QKV16,
        4096, 1024, 1024, 1.f, 4194304, 1048576, 4194304, 1024, nullptr, nullptr);

    // launch 3: transpose V per head
    transposeV<<<dim3(32, 32), 256>>>(QKV16 + 8388608, Vt16);

    // launch 4: scores -> e (fp16, .cs) + per-tile stats
    gemm1<2><<<dim3(16, 16, 32), 256, 40960>>>(
        QKV16, QKV16 + 4194304, nullptr, nullptr, E16,
        2048, 2048, 64, 0.125f, HEAD_STRIDE, HEAD_STRIDE, ATTN_STRIDE, 0, smp, ssp);

    // launch 5: exp-free normalize + P@V (streaming attn writes, fp16 O)
    gemm_pv<<<dim3(1, 16, 32), 256, 30720>>>(E16, attn, Vt16, O16, smp, ssp);

    // launch 6: output projection
    gemm1<0><<<dim3(8, 32, 1), 256, 40960>>>(
        O16, Wo16, bo, proj, nullptr,
        4096, 1024, 1024, 1.f, 0, 0, 0, 0, nullptr, nullptr);
}